// round 8
// baseline (speedup 1.0000x reference)
#include <cuda_runtime.h>
#include <cstdint>

// Problem constants
#define NN   100000   // nodes
#define RR   4        // relations
#define EE   500000   // edges per relation
#define FIN  256
#define FHID 128
#define FOUT 64

// ---------------------------------------------------------------------------
// Scratch (static device globals; allocation-free per harness rules).
// CRITICAL: these symbols are ONLY referenced from device code. Passing them
// as kernel arguments from host code yields the host shadow address — which
// on GB300 (ATS/HMM) is silently dereferenceable and reads/writes HOST memory.
// ---------------------------------------------------------------------------
__device__ __align__(256) float g_dinv_out[RR * NN];          // rsqrt(out-degree)
__device__ __align__(256) float g_dinv_in [RR * NN];          // rsqrt(in-degree)
__device__ __align__(256) float g_h   [(size_t)NN * FHID];    // per-relation transform (reused)
__device__ __align__(256) float g_acc1[(size_t)NN * FHID];    // layer-1 aggregate
__device__ __align__(256) float g_sb1[FHID];                  // sum_r b1[r]
__device__ __align__(256) float g_sb2[FOUT];                  // sum_r b2[r]

// ---------------------------------------------------------------------------
// Zero scratch + output (d_out is poisoned 0xAA before timing)
// ---------------------------------------------------------------------------
__global__ void zero_all(float4* __restrict__ out4) {
    int i = blockIdx.x * blockDim.x + threadIdx.x;
    int stride = gridDim.x * blockDim.x;
    float4 z = make_float4(0.f, 0.f, 0.f, 0.f);
    float4* dout4 = (float4*)g_dinv_out;
    float4* din4  = (float4*)g_dinv_in;
    float4* acc4  = (float4*)g_acc1;
    for (int j = i; j < (RR * NN) / 4; j += stride) { dout4[j] = z; din4[j] = z; }
    for (int j = i; j < (NN * FHID) / 4; j += stride) acc4[j] = z;
    for (int j = i; j < (NN * FOUT) / 4; j += stride) out4[j] = z;
}

// ---------------------------------------------------------------------------
// Degrees: one thread per (relation, edge)
// ---------------------------------------------------------------------------
__global__ void degree_kernel(const int* __restrict__ src, const int* __restrict__ dst) {
    int t = blockIdx.x * blockDim.x + threadIdx.x;
    if (t >= RR * EE) return;
    int r = t / EE;
    atomicAdd(&g_dinv_out[r * NN + src[t]], 1.0f);
    atomicAdd(&g_dinv_in [r * NN + dst[t]], 1.0f);
}

__global__ void rsqrt_kernel() {
    int t = blockIdx.x * blockDim.x + threadIdx.x;
    if (t >= RR * NN) return;
    g_dinv_out[t] = rsqrtf(fmaxf(g_dinv_out[t], 1.0f));
    g_dinv_in [t] = rsqrtf(fmaxf(g_dinv_in [t], 1.0f));
}

// ---------------------------------------------------------------------------
// Bias sums: sb1[n] = sum_r b1[r][n]; sb2[n] = sum_r b2[r][n]
// ---------------------------------------------------------------------------
__global__ void bias_sums(const float* __restrict__ b1, const float* __restrict__ b2) {
    int n = threadIdx.x;
    if (n < FHID) {
        float s = 0.f;
        #pragma unroll
        for (int r = 0; r < RR; r++) s += b1[r * FHID + n];
        g_sb1[n] = s;
    }
    if (n < FOUT) {
        float s = 0.f;
        #pragma unroll
        for (int r = 0; r < RR; r++) s += b2[r * FOUT + n];
        g_sb2[n] = s;
    }
}

// ---------------------------------------------------------------------------
// Tiled SGEMM (one relation r per launch), writes g_h:
//   g_h[m][n] = g_dinv_out[r][m] * sum_k f(A[m][k]) * W[r][k][n]
// LAYER2: A is g_acc1 (device symbol, referenced in device code) and
//         f(a) = relu(a + g_sb1[k]);   else A = A_in (harness pointer), f = id.
// BM=128, TM=8 fixed; BN = full N (one block column); 256 threads.
// ---------------------------------------------------------------------------
template <int BK, int BN, int TN, bool LAYER2>
__global__ void __launch_bounds__(256)
gemm_rgcn(const float* __restrict__ A_in,    // [M][K] (layer-1 only)
          const float* __restrict__ W,       // [R][K][BN]
          int M, int K, int r)
{
    constexpr int BM = 128, TM = 8;
    constexpr int THREADS = (BM / TM) * (BN / TN);
    static_assert(THREADS == 256, "thread count");
    constexpr int AF4 = BM * BK / 4;
    constexpr int BF4 = BK * BN / 4;
    static_assert(AF4 % THREADS == 0 && BF4 % THREADS == 0, "tile loads");

    __shared__ float As[BK][BM];
    __shared__ float Bs[BK][BN];

    const float* A = LAYER2 ? g_acc1 : A_in;   // device-side symbol resolution
    float*       C = g_h;

    const int tid = threadIdx.x;
    const int rowBase = blockIdx.x * BM;
    const float* B = W + (size_t)r * K * BN;

    const int ty = tid / (BN / TN);
    const int tx = tid % (BN / TN);

    float acc[TM][TN];
    #pragma unroll
    for (int i = 0; i < TM; i++)
        #pragma unroll
        for (int j = 0; j < TN; j++) acc[i][j] = 0.f;

    for (int k0 = 0; k0 < K; k0 += BK) {
        // ---- load A tile (transposed into As[k][m]) ----
        #pragma unroll
        for (int i = 0; i < AF4 / THREADS; i++) {
            int f = i * THREADS + tid;
            int arow = f / (BK / 4);
            int ac4  = f % (BK / 4);
            int grow = rowBase + arow;
            float4 v = make_float4(0.f, 0.f, 0.f, 0.f);
            if (grow < M)
                v = *(const float4*)(A + (size_t)grow * K + k0 + ac4 * 4);
            if (LAYER2) {
                const float* bb = g_sb1 + k0 + ac4 * 4;
                v.x = fmaxf(v.x + bb[0], 0.f);
                v.y = fmaxf(v.y + bb[1], 0.f);
                v.z = fmaxf(v.z + bb[2], 0.f);
                v.w = fmaxf(v.w + bb[3], 0.f);
            }
            As[ac4 * 4 + 0][arow] = v.x;
            As[ac4 * 4 + 1][arow] = v.y;
            As[ac4 * 4 + 2][arow] = v.z;
            As[ac4 * 4 + 3][arow] = v.w;
        }
        // ---- load B tile ----
        #pragma unroll
        for (int i = 0; i < BF4 / THREADS; i++) {
            int f = i * THREADS + tid;
            int brow = f / (BN / 4);
            int bc4  = f % (BN / 4);
            *(float4*)&Bs[brow][bc4 * 4] =
                *(const float4*)(B + (size_t)(k0 + brow) * BN + bc4 * 4);
        }
        __syncthreads();

        // ---- compute ----
        #pragma unroll
        for (int k = 0; k < BK; k++) {
            float ra[TM], rb[TN];
            *(float4*)&ra[0] = *(const float4*)&As[k][ty * TM];
            *(float4*)&ra[4] = *(const float4*)&As[k][ty * TM + 4];
            #pragma unroll
            for (int j = 0; j < TN; j += 4)
                *(float4*)&rb[j] = *(const float4*)&Bs[k][tx * TN + j];
            #pragma unroll
            for (int i = 0; i < TM; i++)
                #pragma unroll
                for (int j = 0; j < TN; j++)
                    acc[i][j] = fmaf(ra[i], rb[j], acc[i][j]);
        }
        __syncthreads();
    }

    // ---- epilogue: scale by D_out^{-1/2}[r][row] and store ----
    #pragma unroll
    for (int i = 0; i < TM; i++) {
        int grow = rowBase + ty * TM + i;
        if (grow >= M) break;
        float s = g_dinv_out[(size_t)r * NN + grow];
        float* crow = C + (size_t)grow * BN + tx * TN;
        #pragma unroll
        for (int j = 0; j < TN; j += 4) {
            float4 v = make_float4(acc[i][j] * s, acc[i][j + 1] * s,
                                   acc[i][j + 2] * s, acc[i][j + 3] * s);
            *(float4*)(crow + j) = v;
        }
    }
}

// ---------------------------------------------------------------------------
// Vectorized scatter-add (sm_90+ red.global.add.v4.f32).
// ---------------------------------------------------------------------------
__device__ __forceinline__ void red_v4(float* p, float4 v) {
    asm volatile("{\n\t"
                 ".reg .u64 ga;\n\t"
                 "cvta.to.global.u64 ga, %0;\n\t"
                 "red.global.add.v4.f32 [ga], {%1, %2, %3, %4};\n\t"
                 "}"
                 :: "l"(p), "f"(v.x), "f"(v.y), "f"(v.z), "f"(v.w)
                 : "memory");
}

// Layer-1 scatter (one relation): 128 floats/edge, one warp per edge.
//   g_acc1[dst] += g_dinv_in[r][dst] * g_h[src][:]
__global__ void __launch_bounds__(256)
scatter128(const int* __restrict__ src, const int* __restrict__ dst, int r) {
    int gt = blockIdx.x * blockDim.x + threadIdx.x;
    int w = gt >> 5;                 // edge index in [0, E)
    if (w >= EE) return;
    int lane = gt & 31;
    int s = src[w];
    int d = dst[w];
    float sc = g_dinv_in[r * NN + d];
    float4 v = ((const float4*)g_h)[(size_t)s * (FHID / 4) + lane];
    v.x *= sc; v.y *= sc; v.z *= sc; v.w *= sc;
    red_v4((float*)((float4*)g_acc1 + (size_t)d * (FHID / 4) + lane), v);
}

// Layer-2 scatter (one relation): 64 floats/edge, 16 lanes per edge -> d_out.
__global__ void __launch_bounds__(256)
scatter64(const int* __restrict__ src, const int* __restrict__ dst,
          float* __restrict__ out, int r) {
    int gt = blockIdx.x * blockDim.x + threadIdx.x;
    int p = gt >> 4;                 // edge index in [0, E)
    if (p >= EE) return;
    int l16 = gt & 15;
    int s = src[p];
    int d = dst[p];
    float sc = g_dinv_in[r * NN + d];
    float4 v = ((const float4*)g_h)[(size_t)s * (FOUT / 4) + l16];
    v.x *= sc; v.y *= sc; v.z *= sc; v.w *= sc;
    red_v4((float*)((float4*)out + (size_t)d * (FOUT / 4) + l16), v);
}

// Final: out[m][n] += sum_r b2[r][n]
__global__ void bias_add_out(float* __restrict__ out) {
    int t = blockIdx.x * blockDim.x + threadIdx.x;
    if (t >= NN * FOUT) return;
    out[t] += g_sb2[t % FOUT];
}

// ---------------------------------------------------------------------------
// Launch — only genuine harness pointers are passed to kernels.
// ---------------------------------------------------------------------------
extern "C" void kernel_launch(void* const* d_in, const int* in_sizes, int n_in,
                              void* d_out, int out_size) {
    // Resolve inputs by element count (robust to metadata ordering); all
    // sizes are distinct except src/dst (metadata order: src first).
    const float* x = nullptr; const int* esrc = nullptr; const int* edst = nullptr;
    const float* W1 = nullptr; const float* b1 = nullptr;
    const float* W2 = nullptr; const float* b2 = nullptr;
    for (int i = 0; i < n_in; i++) {
        switch (in_sizes[i]) {
            case NN * FIN:       x  = (const float*)d_in[i]; break;
            case RR * EE:        if (!esrc) esrc = (const int*)d_in[i];
                                 else       edst = (const int*)d_in[i]; break;
            case RR * FIN * FHID:  W1 = (const float*)d_in[i]; break;
            case RR * FHID:        b1 = (const float*)d_in[i]; break;
            case RR * FHID * FOUT: W2 = (const float*)d_in[i]; break;
            case RR * FOUT:        b2 = (const float*)d_in[i]; break;
            default: break;
        }
    }
    if (!x || !esrc || !edst || !W1 || !b1 || !W2 || !b2) {
        x    = (const float*)d_in[0];
        esrc = (const int*)  d_in[1];
        edst = (const int*)  d_in[2];
        W1   = (const float*)d_in[3];
        b1   = (const float*)d_in[4];
        W2   = (const float*)d_in[5];
        b2   = (const float*)d_in[6];
    }
    float* out = (float*)d_out;

    // 1) zero scratch + output
    zero_all<<<2048, 256>>>((float4*)out);

    // 2) degrees -> rsqrt(max(deg,1))
    degree_kernel<<<(RR * EE + 255) / 256, 256>>>(esrc, edst);
    rsqrt_kernel<<<(RR * NN + 255) / 256, 256>>>();

    // 3) bias sums
    bias_sums<<<1, 128>>>(b1, b2);

    dim3 ggrid((NN + 127) / 128, 1, 1);

    // 4) layer 1, per relation: g_h = D_out^{-1/2} (x @ W1[r]);
    //    g_acc1[dst] += D_in^{-1/2}[dst] * g_h[src]
    for (int r = 0; r < RR; r++) {
        gemm_rgcn<16, FHID, 8, false><<<ggrid, 256>>>(x, W1, NN, FIN, r);
        scatter128<<<(EE * 32 + 255) / 256, 256>>>(esrc + r * EE, edst + r * EE, r);
    }

    // 5) layer 2, per relation, fused relu(g_acc1 + g_sb1) on the A-load:
    //    g_h = D_out^{-1/2} (relu(acc1+sb1) @ W2[r]); out[dst] += D_in^{-1/2} g_h[src]
    for (int r = 0; r < RR; r++) {
        gemm_rgcn<16, FOUT, 4, true><<<ggrid, 256>>>(nullptr, W2, NN, FHID, r);
        scatter64<<<(EE * 16 + 255) / 256, 256>>>(esrc + r * EE, edst + r * EE, out, r);
    }

    // 6) final bias
    bias_add_out<<<(NN * FOUT + 255) / 256, 256>>>(out);
}

// round 10
// speedup vs baseline: 1.7142x; 1.7142x over previous
#include <cuda_runtime.h>
#include <cstdint>

// Problem constants
#define NN   100000   // nodes
#define RR   4        // relations
#define EE   500000   // edges per relation
#define FIN  256
#define FHID 128
#define FOUT 64

// ---------------------------------------------------------------------------
// Scratch (static device globals). ONLY referenced from device code — passing
// these symbols as kernel args from host code yields the host-shadow address,
// which GB300 ATS silently dereferences into HOST memory (R5/R6 bug).
// ---------------------------------------------------------------------------
__device__ __align__(256) float g_dinv_out[RR * NN];          // rsqrt(out-degree)
__device__ __align__(256) float g_dinv_in [RR * NN];          // rsqrt(in-degree)
__device__ __align__(256) float g_h   [(size_t)NN * FHID];    // per-relation transform (reused)
__device__ __align__(256) float g_acc1[(size_t)NN * FHID];    // layer-1 aggregate
__device__ __align__(256) float g_sb1[FHID];                  // sum_r b1[r]
__device__ __align__(256) float g_sb2[FOUT];                  // sum_r b2[r]

// ---------------------------------------------------------------------------
// Zero scratch + output
// ---------------------------------------------------------------------------
__global__ void zero_all(float4* __restrict__ out4) {
    int i = blockIdx.x * blockDim.x + threadIdx.x;
    int stride = gridDim.x * blockDim.x;
    float4 z = make_float4(0.f, 0.f, 0.f, 0.f);
    float4* dout4 = (float4*)g_dinv_out;
    float4* din4  = (float4*)g_dinv_in;
    float4* acc4  = (float4*)g_acc1;
    for (int j = i; j < (RR * NN) / 4; j += stride) { dout4[j] = z; din4[j] = z; }
    for (int j = i; j < (NN * FHID) / 4; j += stride) acc4[j] = z;
    for (int j = i; j < (NN * FOUT) / 4; j += stride) out4[j] = z;
}

// ---------------------------------------------------------------------------
// Degrees
// ---------------------------------------------------------------------------
__global__ void degree_kernel(const int* __restrict__ src, const int* __restrict__ dst) {
    int t = blockIdx.x * blockDim.x + threadIdx.x;
    if (t >= RR * EE) return;
    int r = t / EE;
    atomicAdd(&g_dinv_out[r * NN + src[t]], 1.0f);
    atomicAdd(&g_dinv_in [r * NN + dst[t]], 1.0f);
}

__global__ void rsqrt_kernel() {
    int t = blockIdx.x * blockDim.x + threadIdx.x;
    if (t >= RR * NN) return;
    g_dinv_out[t] = rsqrtf(fmaxf(g_dinv_out[t], 1.0f));
    g_dinv_in [t] = rsqrtf(fmaxf(g_dinv_in [t], 1.0f));
}

// ---------------------------------------------------------------------------
// Bias sums
// ---------------------------------------------------------------------------
__global__ void bias_sums(const float* __restrict__ b1, const float* __restrict__ b2) {
    int n = threadIdx.x;
    if (n < FHID) {
        float s = 0.f;
        #pragma unroll
        for (int r = 0; r < RR; r++) s += b1[r * FHID + n];
        g_sb1[n] = s;
    }
    if (n < FOUT) {
        float s = 0.f;
        #pragma unroll
        for (int r = 0; r < RR; r++) s += b2[r * FOUT + n];
        g_sb2[n] = s;
    }
}

// ---------------------------------------------------------------------------
// TF32 helpers
// ---------------------------------------------------------------------------
__device__ __forceinline__ uint32_t f2tf32(float x) {
    uint32_t u;
    asm("cvt.rna.tf32.f32 %0, %1;" : "=r"(u) : "f"(x));
    return u;
}

__device__ __forceinline__ void mma_tf32(float* c, const uint32_t* a,
                                         uint32_t b0, uint32_t b1) {
    asm volatile(
        "mma.sync.aligned.m16n8k8.row.col.f32.tf32.tf32.f32 "
        "{%0,%1,%2,%3}, {%4,%5,%6,%7}, {%8,%9}, {%0,%1,%2,%3};"
        : "+f"(c[0]), "+f"(c[1]), "+f"(c[2]), "+f"(c[3])
        : "r"(a[0]), "r"(a[1]), "r"(a[2]), "r"(a[3]), "r"(b0), "r"(b1));
}

// ---------------------------------------------------------------------------
// Tensor-core TF32 GEMM (one relation r per launch), writes g_h:
//   g_h[m][n] = g_dinv_out[r][m] * sum_k f(A[m][k]) * W[r][k][n]
// LAYER2: A = g_acc1 (device symbol), f(a) = relu(a + g_sb1[k]); else A=A_in.
// BM=128, BK=32, 256 threads = 8 warps (4 m x 2 n). Warp tile 32 x (BN/2).
// Register-staged prefetch of the next K-tile overlaps LDG with HMMA.
// Smem strides padded for conflict-free fragment loads:
//   As stride 36: bank = (4g + tig) -> 32 distinct lanes
//   Bs stride BN+8: bank = (8*tig + g) -> 32 distinct lanes
// ---------------------------------------------------------------------------
template <int BN, bool LAYER2>
__global__ void __launch_bounds__(256, 2)
gemm_tc(const float* __restrict__ A_in,   // [M][K] (layer-1 only)
        const float* __restrict__ W,      // [R][K][BN]
        int M, int K, int r)
{
    constexpr int BM = 128, BK = 32;
    constexpr int APT  = BM * BK / 4 / 256;   // float4 A-loads per thread (4)
    constexpr int BPT  = BK * BN / 4 / 256;   // float4 B-loads per thread (4|2)
    constexpr int ASTR = BK + 4;              // 36 floats
    constexpr int BSTR = BN + 8;
    constexpr int WN   = BN / 2;              // warp n-extent
    constexpr int NT   = WN / 8;              // n-tiles per warp (8|4)

    __shared__ uint32_t As[BM * ASTR];
    __shared__ uint32_t Bs[BK * BSTR];

    const float* A = LAYER2 ? g_acc1 : A_in;  // device-side symbol resolution
    const float* B = W + (size_t)r * K * BN;

    const int tid  = threadIdx.x;
    const int wid  = tid >> 5;
    const int lane = tid & 31;
    const int g    = lane >> 2;               // 0..7
    const int tig  = lane & 3;                // 0..3
    const int warp_m = wid & 3;               // 0..3
    const int warp_n = wid >> 2;              // 0..1
    const int rowBase = blockIdx.x * BM;

    float acc[2][NT][4];
    #pragma unroll
    for (int mt = 0; mt < 2; mt++)
        #pragma unroll
        for (int nt = 0; nt < NT; nt++)
            #pragma unroll
            for (int j = 0; j < 4; j++) acc[mt][nt][j] = 0.f;

    float4 aReg[APT], bReg[BPT];

    // ---- tile load (global -> regs) ----
    auto load_regs = [&](int k0) {
        #pragma unroll
        for (int i = 0; i < APT; i++) {
            int f = i * 256 + tid;
            int arow = f >> 3;                // / (BK/4)
            int ac4  = f & 7;
            int grow = rowBase + arow;
            float4 v = make_float4(0.f, 0.f, 0.f, 0.f);
            if (grow < M)
                v = *(const float4*)(A + (size_t)grow * K + k0 + ac4 * 4);
            aReg[i] = v;
        }
        #pragma unroll
        for (int i = 0; i < BPT; i++) {
            int f = i * 256 + tid;
            int brow = f / (BN / 4);
            int bc4  = f % (BN / 4);
            bReg[i] = *(const float4*)(B + (size_t)(k0 + brow) * BN + bc4 * 4);
        }
    };

    // ---- tile store (regs -> smem, tf32 convert, layer-2 bias+relu) ----
    auto store_smem = [&](int kload) {
        #pragma unroll
        for (int i = 0; i < APT; i++) {
            int f = i * 256 + tid;
            int arow = f >> 3;
            int ac4  = f & 7;
            float4 v = aReg[i];
            if (LAYER2) {
                const float* bb = g_sb1 + kload + ac4 * 4;
                v.x = fmaxf(v.x + bb[0], 0.f);
                v.y = fmaxf(v.y + bb[1], 0.f);
                v.z = fmaxf(v.z + bb[2], 0.f);
                v.w = fmaxf(v.w + bb[3], 0.f);
            }
            uint4 u = make_uint4(f2tf32(v.x), f2tf32(v.y), f2tf32(v.z), f2tf32(v.w));
            *(uint4*)&As[arow * ASTR + ac4 * 4] = u;
        }
        #pragma unroll
        for (int i = 0; i < BPT; i++) {
            int f = i * 256 + tid;
            int brow = f / (BN / 4);
            int bc4  = f % (BN / 4);
            float4 v = bReg[i];
            uint4 u = make_uint4(f2tf32(v.x), f2tf32(v.y), f2tf32(v.z), f2tf32(v.w));
            *(uint4*)&Bs[brow * BSTR + bc4 * 4] = u;
        }
    };

    // ---- mma over current smem tile ----
    auto compute = [&]() {
        #pragma unroll
        for (int ks = 0; ks < 4; ks++) {
            int k8 = ks * 8;
            uint32_t a[2][4];
            #pragma unroll
            for (int mt = 0; mt < 2; mt++) {
                int rb = warp_m * 32 + mt * 16;
                a[mt][0] = As[(rb + g)     * ASTR + k8 + tig];
                a[mt][1] = As[(rb + g + 8) * ASTR + k8 + tig];
                a[mt][2] = As[(rb + g)     * ASTR + k8 + tig + 4];
                a[mt][3] = As[(rb + g + 8) * ASTR + k8 + tig + 4];
            }
            #pragma unroll
            for (int nt = 0; nt < NT; nt++) {
                int cb = warp_n * WN + nt * 8;
                uint32_t b0 = Bs[(k8 + tig)     * BSTR + cb + g];
                uint32_t b1 = Bs[(k8 + tig + 4) * BSTR + cb + g];
                #pragma unroll
                for (int mt = 0; mt < 2; mt++)
                    mma_tf32(acc[mt][nt], a[mt], b0, b1);
            }
        }
    };

    // ---- pipelined K loop ----
    load_regs(0);
    store_smem(0);
    __syncthreads();
    for (int k0 = BK; k0 < K; k0 += BK) {
        load_regs(k0);       // LDG for next tile overlaps HMMA below
        compute();
        __syncthreads();
        store_smem(k0);
        __syncthreads();
    }
    compute();

    // ---- epilogue: scale by D_out^{-1/2}[r][row], store to g_h ----
    #pragma unroll
    for (int mt = 0; mt < 2; mt++) {
        int row0 = rowBase + warp_m * 32 + mt * 16 + g;
        int row1 = row0 + 8;
        float s0 = (row0 < M) ? g_dinv_out[(size_t)r * NN + row0] : 0.f;
        float s1 = (row1 < M) ? g_dinv_out[(size_t)r * NN + row1] : 0.f;
        #pragma unroll
        for (int nt = 0; nt < NT; nt++) {
            int col = warp_n * WN + nt * 8 + 2 * tig;
            if (row0 < M)
                *(float2*)&g_h[(size_t)row0 * BN + col] =
                    make_float2(acc[mt][nt][0] * s0, acc[mt][nt][1] * s0);
            if (row1 < M)
                *(float2*)&g_h[(size_t)row1 * BN + col] =
                    make_float2(acc[mt][nt][2] * s1, acc[mt][nt][3] * s1);
        }
    }
}

// ---------------------------------------------------------------------------
// Vectorized scatter-add (red.global.add.v4.f32)
// ---------------------------------------------------------------------------
__device__ __forceinline__ void red_v4(float* p, float4 v) {
    asm volatile("{\n\t"
                 ".reg .u64 ga;\n\t"
                 "cvta.to.global.u64 ga, %0;\n\t"
                 "red.global.add.v4.f32 [ga], {%1, %2, %3, %4};\n\t"
                 "}"
                 :: "l"(p), "f"(v.x), "f"(v.y), "f"(v.z), "f"(v.w)
                 : "memory");
}

// Layer-1 scatter (one relation): g_acc1[dst] += dinv_in[r][dst] * g_h[src]
__global__ void __launch_bounds__(256)
scatter128(const int* __restrict__ src, const int* __restrict__ dst, int r) {
    int gt = blockIdx.x * blockDim.x + threadIdx.x;
    int w = gt >> 5;
    if (w >= EE) return;
    int lane = gt & 31;
    int s = src[w];
    int d = dst[w];
    float sc = g_dinv_in[r * NN + d];
    float4 v = ((const float4*)g_h)[(size_t)s * (FHID / 4) + lane];
    v.x *= sc; v.y *= sc; v.z *= sc; v.w *= sc;
    red_v4((float*)((float4*)g_acc1 + (size_t)d * (FHID / 4) + lane), v);
}

// Layer-2 scatter (one relation): out[dst] += dinv_in[r][dst] * g_h[src]
__global__ void __launch_bounds__(256)
scatter64(const int* __restrict__ src, const int* __restrict__ dst,
          float* __restrict__ out, int r) {
    int gt = blockIdx.x * blockDim.x + threadIdx.x;
    int p = gt >> 4;
    if (p >= EE) return;
    int l16 = gt & 15;
    int s = src[p];
    int d = dst[p];
    float sc = g_dinv_in[r * NN + d];
    float4 v = ((const float4*)g_h)[(size_t)s * (FOUT / 4) + l16];
    v.x *= sc; v.y *= sc; v.z *= sc; v.w *= sc;
    red_v4((float*)((float4*)out + (size_t)d * (FOUT / 4) + l16), v);
}

// Final: out[m][n] += sum_r b2[r][n]
__global__ void bias_add_out(float* __restrict__ out) {
    int t = blockIdx.x * blockDim.x + threadIdx.x;
    if (t >= NN * FOUT) return;
    out[t] += g_sb2[t % FOUT];
}

// ---------------------------------------------------------------------------
// Launch — only genuine harness pointers cross host/device.
// ---------------------------------------------------------------------------
extern "C" void kernel_launch(void* const* d_in, const int* in_sizes, int n_in,
                              void* d_out, int out_size) {
    const float* x = nullptr; const int* esrc = nullptr; const int* edst = nullptr;
    const float* W1 = nullptr; const float* b1 = nullptr;
    const float* W2 = nullptr; const float* b2 = nullptr;
    for (int i = 0; i < n_in; i++) {
        switch (in_sizes[i]) {
            case NN * FIN:       x  = (const float*)d_in[i]; break;
            case RR * EE:        if (!esrc) esrc = (const int*)d_in[i];
                                 else       edst = (const int*)d_in[i]; break;
            case RR * FIN * FHID:  W1 = (const float*)d_in[i]; break;
            case RR * FHID:        b1 = (const float*)d_in[i]; break;
            case RR * FHID * FOUT: W2 = (const float*)d_in[i]; break;
            case RR * FOUT:        b2 = (const float*)d_in[i]; break;
            default: break;
        }
    }
    if (!x || !esrc || !edst || !W1 || !b1 || !W2 || !b2) {
        x    = (const float*)d_in[0];
        esrc = (const int*)  d_in[1];
        edst = (const int*)  d_in[2];
        W1   = (const float*)d_in[3];
        b1   = (const float*)d_in[4];
        W2   = (const float*)d_in[5];
        b2   = (const float*)d_in[6];
    }
    float* out = (float*)d_out;

    // 1) zero scratch + output
    zero_all<<<2048, 256>>>((float4*)out);

    // 2) degrees -> rsqrt(max(deg,1))
    degree_kernel<<<(RR * EE + 255) / 256, 256>>>(esrc, edst);
    rsqrt_kernel<<<(RR * NN + 255) / 256, 256>>>();

    // 3) bias sums
    bias_sums<<<1, 128>>>(b1, b2);

    dim3 ggrid((NN + 127) / 128, 1, 1);

    // 4) layer 1, per relation (g_h stays L2-resident for the scatter):
    //    g_h = D_out^{-1/2} (x @ W1[r]);  g_acc1[dst] += D_in^{-1/2}[dst] g_h[src]
    for (int r = 0; r < RR; r++) {
        gemm_tc<FHID, false><<<ggrid, 256>>>(x, W1, NN, FIN, r);
        scatter128<<<(EE * 32 + 255) / 256, 256>>>(esrc + r * EE, edst + r * EE, r);
    }

    // 5) layer 2, per relation, fused relu(g_acc1 + g_sb1) at the A-stage:
    //    g_h = D_out^{-1/2} (relu(acc1+sb1) @ W2[r]); out[dst] += D_in^{-1/2} g_h[src]
    for (int r = 0; r < RR; r++) {
        gemm_tc<FOUT, true><<<ggrid, 256>>>(nullptr, W2, NN, FHID, r);
        scatter64<<<(EE * 16 + 255) / 256, 256>>>(esrc + r * EE, edst + r * EE, out, r);
    }

    // 6) final bias
    bias_add_out<<<(NN * FOUT + 255) / 256, 256>>>(out);
}

// round 11
// speedup vs baseline: 1.7950x; 1.0472x over previous
#include <cuda_runtime.h>
#include <cuda_fp16.h>
#include <cstdint>

// Problem constants
#define NN   100000   // nodes
#define RR   4        // relations
#define EE   500000   // edges per relation
#define FIN  256
#define FHID 128
#define FOUT 64

// ---------------------------------------------------------------------------
// Scratch (static device globals). ONLY referenced from device code — passing
// these symbols as kernel args from host code yields the host-shadow address,
// which GB300 ATS silently dereferences into HOST memory (R5/R6 bug).
// ---------------------------------------------------------------------------
__device__ __align__(256) float  g_dinv_out[RR * NN];          // rsqrt(out-degree)
__device__ __align__(256) float  g_dinv_in [RR * NN];          // rsqrt(in-degree)
__device__ __align__(256) __half g_h16[(size_t)NN * FHID];     // per-relation transform (fp16, reused)
__device__ __align__(256) float  g_acc1[(size_t)NN * FHID];    // layer-1 aggregate (fp32)
__device__ __align__(256) float  g_sb1[FHID];                  // sum_r b1[r]

// ---------------------------------------------------------------------------
// Zero scratch; initialize out[m][n] = sum_r b2[r][n] (replaces final bias kernel)
// ---------------------------------------------------------------------------
__global__ void zero_all(float4* __restrict__ out4, const float* __restrict__ b2) {
    int i = blockIdx.x * blockDim.x + threadIdx.x;
    int stride = gridDim.x * blockDim.x;
    float4 z = make_float4(0.f, 0.f, 0.f, 0.f);
    float4* dout4 = (float4*)g_dinv_out;
    float4* din4  = (float4*)g_dinv_in;
    float4* acc4  = (float4*)g_acc1;
    for (int j = i; j < (RR * NN) / 4; j += stride) { dout4[j] = z; din4[j] = z; }
    for (int j = i; j < (NN * FHID) / 4; j += stride) acc4[j] = z;
    for (int j = i; j < (NN * FOUT) / 4; j += stride) {
        int c = (j % (FOUT / 4)) * 4;          // column of first element
        float4 v;
        v.x = b2[c+0] + b2[FOUT+c+0] + b2[2*FOUT+c+0] + b2[3*FOUT+c+0];
        v.y = b2[c+1] + b2[FOUT+c+1] + b2[2*FOUT+c+1] + b2[3*FOUT+c+1];
        v.z = b2[c+2] + b2[FOUT+c+2] + b2[2*FOUT+c+2] + b2[3*FOUT+c+2];
        v.w = b2[c+3] + b2[FOUT+c+3] + b2[2*FOUT+c+3] + b2[3*FOUT+c+3];
        out4[j] = v;
    }
}

// ---------------------------------------------------------------------------
// Degrees
// ---------------------------------------------------------------------------
__global__ void degree_kernel(const int* __restrict__ src, const int* __restrict__ dst) {
    int t = blockIdx.x * blockDim.x + threadIdx.x;
    if (t >= RR * EE) return;
    int r = t / EE;
    atomicAdd(&g_dinv_out[r * NN + src[t]], 1.0f);
    atomicAdd(&g_dinv_in [r * NN + dst[t]], 1.0f);
}

// rsqrt of degrees + fold in sb1 = sum_r b1[r] (merged to cut a launch)
__global__ void rsqrt_kernel(const float* __restrict__ b1) {
    int t = blockIdx.x * blockDim.x + threadIdx.x;
    if (t < FHID) {
        float s = 0.f;
        #pragma unroll
        for (int r = 0; r < RR; r++) s += b1[r * FHID + t];
        g_sb1[t] = s;
    }
    if (t >= RR * NN) return;
    g_dinv_out[t] = rsqrtf(fmaxf(g_dinv_out[t], 1.0f));
    g_dinv_in [t] = rsqrtf(fmaxf(g_dinv_in [t], 1.0f));
}

// ---------------------------------------------------------------------------
// TF32 helpers
// ---------------------------------------------------------------------------
__device__ __forceinline__ uint32_t f2tf32(float x) {
    uint32_t u;
    asm("cvt.rna.tf32.f32 %0, %1;" : "=r"(u) : "f"(x));
    return u;
}

__device__ __forceinline__ void mma_tf32(float* c, const uint32_t* a,
                                         uint32_t b0, uint32_t b1) {
    asm volatile(
        "mma.sync.aligned.m16n8k8.row.col.f32.tf32.tf32.f32 "
        "{%0,%1,%2,%3}, {%4,%5,%6,%7}, {%8,%9}, {%0,%1,%2,%3};"
        : "+f"(c[0]), "+f"(c[1]), "+f"(c[2]), "+f"(c[3])
        : "r"(a[0]), "r"(a[1]), "r"(a[2]), "r"(a[3]), "r"(b0), "r"(b1));
}

// ---------------------------------------------------------------------------
// Tensor-core TF32 GEMM (one relation r per launch), writes g_h16 (fp16):
//   g_h16[m][n] = half( g_dinv_out[r][m] * sum_k f(A[m][k]) * W[r][k][n] )
// LAYER2: A = g_acc1 (device symbol), f(a) = relu(a + g_sb1[k]); else A=A_in.
// BM=128, BK=32, 256 threads = 8 warps (4 m x 2 n). Warp tile 32 x (BN/2).
// Register-staged prefetch of the next K-tile overlaps LDG with HMMA.
// Smem strides padded for conflict-free fragment loads:
//   As stride 36: bank = (4g + tig) -> 32 distinct lanes
//   Bs stride BN+8: bank = (8*tig + g) -> 32 distinct lanes
// ---------------------------------------------------------------------------
template <int BN, bool LAYER2>
__global__ void __launch_bounds__(256, 2)
gemm_tc(const float* __restrict__ A_in,   // [M][K] (layer-1 only)
        const float* __restrict__ W,      // [R][K][BN]
        int M, int K, int r)
{
    constexpr int BM = 128, BK = 32;
    constexpr int APT  = BM * BK / 4 / 256;   // float4 A-loads per thread (4)
    constexpr int BPT  = BK * BN / 4 / 256;   // float4 B-loads per thread (4|2)
    constexpr int ASTR = BK + 4;              // 36
    constexpr int BSTR = BN + 8;
    constexpr int WN   = BN / 2;              // warp n-extent
    constexpr int NT   = WN / 8;              // n-tiles per warp (8|4)

    __shared__ uint32_t As[BM * ASTR];
    __shared__ uint32_t Bs[BK * BSTR];

    const float* A = LAYER2 ? g_acc1 : A_in;  // device-side symbol resolution
    const float* B = W + (size_t)r * K * BN;

    const int tid  = threadIdx.x;
    const int wid  = tid >> 5;
    const int lane = tid & 31;
    const int g    = lane >> 2;               // 0..7
    const int tig  = lane & 3;                // 0..3
    const int warp_m = wid & 3;               // 0..3
    const int warp_n = wid >> 2;              // 0..1
    const int rowBase = blockIdx.x * BM;

    float acc[2][NT][4];
    #pragma unroll
    for (int mt = 0; mt < 2; mt++)
        #pragma unroll
        for (int nt = 0; nt < NT; nt++)
            #pragma unroll
            for (int j = 0; j < 4; j++) acc[mt][nt][j] = 0.f;

    float4 aReg[APT], bReg[BPT];

    auto load_regs = [&](int k0) {
        #pragma unroll
        for (int i = 0; i < APT; i++) {
            int f = i * 256 + tid;
            int arow = f >> 3;
            int ac4  = f & 7;
            int grow = rowBase + arow;
            float4 v = make_float4(0.f, 0.f, 0.f, 0.f);
            if (grow < M)
                v = *(const float4*)(A + (size_t)grow * K + k0 + ac4 * 4);
            aReg[i] = v;
        }
        #pragma unroll
        for (int i = 0; i < BPT; i++) {
            int f = i * 256 + tid;
            int brow = f / (BN / 4);
            int bc4  = f % (BN / 4);
            bReg[i] = *(const float4*)(B + (size_t)(k0 + brow) * BN + bc4 * 4);
        }
    };

    auto store_smem = [&](int kload) {
        #pragma unroll
        for (int i = 0; i < APT; i++) {
            int f = i * 256 + tid;
            int arow = f >> 3;
            int ac4  = f & 7;
            float4 v = aReg[i];
            if (LAYER2) {
                const float* bb = g_sb1 + kload + ac4 * 4;
                v.x = fmaxf(v.x + bb[0], 0.f);
                v.y = fmaxf(v.y + bb[1], 0.f);
                v.z = fmaxf(v.z + bb[2], 0.f);
                v.w = fmaxf(v.w + bb[3], 0.f);
            }
            uint4 u = make_uint4(f2tf32(v.x), f2tf32(v.y), f2tf32(v.z), f2tf32(v.w));
            *(uint4*)&As[arow * ASTR + ac4 * 4] = u;
        }
        #pragma unroll
        for (int i = 0; i < BPT; i++) {
            int f = i * 256 + tid;
            int brow = f / (BN / 4);
            int bc4  = f % (BN / 4);
            float4 v = bReg[i];
            uint4 u = make_uint4(f2tf32(v.x), f2tf32(v.y), f2tf32(v.z), f2tf32(v.w));
            *(uint4*)&Bs[brow * BSTR + bc4 * 4] = u;
        }
    };

    auto compute = [&]() {
        #pragma unroll
        for (int ks = 0; ks < 4; ks++) {
            int k8 = ks * 8;
            uint32_t a[2][4];
            #pragma unroll
            for (int mt = 0; mt < 2; mt++) {
                int rb = warp_m * 32 + mt * 16;
                a[mt][0] = As[(rb + g)     * ASTR + k8 + tig];
                a[mt][1] = As[(rb + g + 8) * ASTR + k8 + tig];
                a[mt][2] = As[(rb + g)     * ASTR + k8 + tig + 4];
                a[mt][3] = As[(rb + g + 8) * ASTR + k8 + tig + 4];
            }
            #pragma unroll
            for (int nt = 0; nt < NT; nt++) {
                int cb = warp_n * WN + nt * 8;
                uint32_t b0 = Bs[(k8 + tig)     * BSTR + cb + g];
                uint32_t b1 = Bs[(k8 + tig + 4) * BSTR + cb + g];
                #pragma unroll
                for (int mt = 0; mt < 2; mt++)
                    mma_tf32(acc[mt][nt], a[mt], b0, b1);
            }
        }
    };

    // ---- pipelined K loop ----
    load_regs(0);
    store_smem(0);
    __syncthreads();
    for (int k0 = BK; k0 < K; k0 += BK) {
        load_regs(k0);       // LDG for next tile overlaps HMMA below
        compute();
        __syncthreads();
        store_smem(k0);
        __syncthreads();
    }
    compute();

    // ---- epilogue: scale by D_out^{-1/2}[r][row], store fp16 to g_h16 ----
    #pragma unroll
    for (int mt = 0; mt < 2; mt++) {
        int row0 = rowBase + warp_m * 32 + mt * 16 + g;
        int row1 = row0 + 8;
        float s0 = (row0 < M) ? g_dinv_out[(size_t)r * NN + row0] : 0.f;
        float s1 = (row1 < M) ? g_dinv_out[(size_t)r * NN + row1] : 0.f;
        #pragma unroll
        for (int nt = 0; nt < NT; nt++) {
            int col = warp_n * WN + nt * 8 + 2 * tig;   // even -> 4B aligned half2
            if (row0 < M)
                *(__half2*)&g_h16[(size_t)row0 * BN + col] =
                    __floats2half2_rn(acc[mt][nt][0] * s0, acc[mt][nt][1] * s0);
            if (row1 < M)
                *(__half2*)&g_h16[(size_t)row1 * BN + col] =
                    __floats2half2_rn(acc[mt][nt][2] * s1, acc[mt][nt][3] * s1);
        }
    }
}

// ---------------------------------------------------------------------------
// Vectorized scatter-add (red.global.add.v4.f32)
// ---------------------------------------------------------------------------
__device__ __forceinline__ void red_v4(float* p, float4 v) {
    asm volatile("{\n\t"
                 ".reg .u64 ga;\n\t"
                 "cvta.to.global.u64 ga, %0;\n\t"
                 "red.global.add.v4.f32 [ga], {%1, %2, %3, %4};\n\t"
                 "}"
                 :: "l"(p), "f"(v.x), "f"(v.y), "f"(v.z), "f"(v.w)
                 : "memory");
}

__device__ __forceinline__ float4 h4_to_f4(uint2 raw, float sc) {
    __half2 h01 = *(__half2*)&raw.x;
    __half2 h23 = *(__half2*)&raw.y;
    float2 f01 = __half22float2(h01);
    float2 f23 = __half22float2(h23);
    return make_float4(f01.x * sc, f01.y * sc, f23.x * sc, f23.y * sc);
}

// Layer-1 scatter (one relation): g_acc1[dst] += dinv_in[r][dst] * h16[src]
// 128 halfs/row = 32 uint2; one warp per edge, lane handles 4 features.
__global__ void __launch_bounds__(256)
scatter128(const int* __restrict__ src, const int* __restrict__ dst, int r) {
    int gt = blockIdx.x * blockDim.x + threadIdx.x;
    int w = gt >> 5;
    if (w >= EE) return;
    int lane = gt & 31;
    int s = src[w];
    int d = dst[w];
    float sc = g_dinv_in[r * NN + d];
    uint2 raw = ((const uint2*)g_h16)[(size_t)s * (FHID / 4) + lane];
    float4 v = h4_to_f4(raw, sc);
    red_v4((float*)((float4*)g_acc1 + (size_t)d * (FHID / 4) + lane), v);
}

// Layer-2 scatter (one relation): out[dst] += dinv_in[r][dst] * h16[src]
// 64 halfs/row = 16 uint2; 16 lanes per edge.
__global__ void __launch_bounds__(256)
scatter64(const int* __restrict__ src, const int* __restrict__ dst,
          float* __restrict__ out, int r) {
    int gt = blockIdx.x * blockDim.x + threadIdx.x;
    int p = gt >> 4;
    if (p >= EE) return;
    int l16 = gt & 15;
    int s = src[p];
    int d = dst[p];
    float sc = g_dinv_in[r * NN + d];
    uint2 raw = ((const uint2*)g_h16)[(size_t)s * (FOUT / 4) + l16];
    float4 v = h4_to_f4(raw, sc);
    red_v4((float*)((float4*)out + (size_t)d * (FOUT / 4) + l16), v);
}

// ---------------------------------------------------------------------------
// Launch — only genuine harness pointers cross host/device.
// ---------------------------------------------------------------------------
extern "C" void kernel_launch(void* const* d_in, const int* in_sizes, int n_in,
                              void* d_out, int out_size) {
    const float* x = nullptr; const int* esrc = nullptr; const int* edst = nullptr;
    const float* W1 = nullptr; const float* b1 = nullptr;
    const float* W2 = nullptr; const float* b2 = nullptr;
    for (int i = 0; i < n_in; i++) {
        switch (in_sizes[i]) {
            case NN * FIN:       x  = (const float*)d_in[i]; break;
            case RR * EE:        if (!esrc) esrc = (const int*)d_in[i];
                                 else       edst = (const int*)d_in[i]; break;
            case RR * FIN * FHID:  W1 = (const float*)d_in[i]; break;
            case RR * FHID:        b1 = (const float*)d_in[i]; break;
            case RR * FHID * FOUT: W2 = (const float*)d_in[i]; break;
            case RR * FOUT:        b2 = (const float*)d_in[i]; break;
            default: break;
        }
    }
    if (!x || !esrc || !edst || !W1 || !b1 || !W2 || !b2) {
        x    = (const float*)d_in[0];
        esrc = (const int*)  d_in[1];
        edst = (const int*)  d_in[2];
        W1   = (const float*)d_in[3];
        b1   = (const float*)d_in[4];
        W2   = (const float*)d_in[5];
        b2   = (const float*)d_in[6];
    }
    float* out = (float*)d_out;

    // 1) zero scratch; out <- broadcast sum_r b2[r]
    zero_all<<<2048, 256>>>((float4*)out, b2);

    // 2) degrees -> rsqrt(max(deg,1)); also computes g_sb1
    degree_kernel<<<(RR * EE + 255) / 256, 256>>>(esrc, edst);
    rsqrt_kernel<<<(RR * NN + 255) / 256, 256>>>(b1);

    dim3 ggrid((NN + 127) / 128, 1, 1);

    // 3) layer 1, per relation (g_h16 + g_acc1 stay L2-resident):
    //    h = D_out^{-1/2} (x @ W1[r]);  acc1[dst] += D_in^{-1/2}[dst] h[src]
    for (int r = 0; r < RR; r++) {
        gemm_tc<FHID, false><<<ggrid, 256>>>(x, W1, NN, FIN, r);
        scatter128<<<(EE * 32 + 255) / 256, 256>>>(esrc + r * EE, edst + r * EE, r);
    }

    // 4) layer 2, per relation, fused relu(acc1 + sb1) at the A-stage:
    //    h = D_out^{-1/2} (relu(acc1+sb1) @ W2[r]); out[dst] += D_in^{-1/2} h[src]
    for (int r = 0; r < RR; r++) {
        gemm_tc<FOUT, true><<<ggrid, 256>>>(nullptr, W2, NN, FHID, r);
        scatter64<<<(EE * 16 + 255) / 256, 256>>>(esrc + r * EE, edst + r * EE, out, r);
    }
}

// round 12
// speedup vs baseline: 2.1171x; 1.1794x over previous
#include <cuda_runtime.h>
#include <cuda_fp16.h>
#include <cstdint>

// Problem constants
#define NN   100000   // nodes
#define RR   4        // relations
#define EE   500000   // edges per relation
#define FIN  256
#define FHID 128
#define FOUT 64

#define NSC  (RR * NN)                   // scan length (400000)
#define NB   ((NSC + 1023) / 1024)       // scan blocks (391)

// ---------------------------------------------------------------------------
// Scratch (static device globals). ONLY referenced from device code — passing
// these symbols as kernel args from host code yields the host-shadow address,
// which GB300 ATS silently dereferences into HOST memory (R5/R6 bug).
// ---------------------------------------------------------------------------
__device__ __align__(256) float  g_dinv_out[RR * NN];          // rsqrt(out-degree)
__device__ __align__(256) float  g_dinv_in [RR * NN];          // rsqrt(in-degree)
__device__ __align__(256) __half g_h16[(size_t)NN * FHID];     // per-relation transform (fp16)
__device__ __align__(256) float  g_acc1[(size_t)NN * FHID];    // layer-1 aggregate (fp32)
__device__ __align__(256) float  g_sb1[FHID];                  // sum_r b1[r]
// CSR build
__device__ __align__(256) int    g_cnt   [NSC];                // dst histogram per relation
__device__ __align__(256) int    g_rowptr[NSC];                // exclusive scan of g_cnt
__device__ __align__(256) int    g_wptr  [NSC];                // write cursors (placement)
__device__ __align__(256) int    g_bsum  [512];                // scan block sums
__device__ __align__(256) int    g_srt   [RR * EE];            // src ids, dst-sorted per relation

// ---------------------------------------------------------------------------
// Zero scratch; initialize out[m][n] = sum_r b2[r][n]
// ---------------------------------------------------------------------------
__global__ void zero_all(float4* __restrict__ out4, const float* __restrict__ b2) {
    int i = blockIdx.x * blockDim.x + threadIdx.x;
    int stride = gridDim.x * blockDim.x;
    float4 z = make_float4(0.f, 0.f, 0.f, 0.f);
    float4* dout4 = (float4*)g_dinv_out;
    int4*   cnt4  = (int4*)g_cnt;
    float4* acc4  = (float4*)g_acc1;
    int4 zi = make_int4(0, 0, 0, 0);
    for (int j = i; j < NSC / 4; j += stride) { dout4[j] = z; cnt4[j] = zi; }
    for (int j = i; j < (NN * FHID) / 4; j += stride) acc4[j] = z;
    for (int j = i; j < (NN * FOUT) / 4; j += stride) {
        int c = (j % (FOUT / 4)) * 4;
        float4 v;
        v.x = b2[c+0] + b2[FOUT+c+0] + b2[2*FOUT+c+0] + b2[3*FOUT+c+0];
        v.y = b2[c+1] + b2[FOUT+c+1] + b2[2*FOUT+c+1] + b2[3*FOUT+c+1];
        v.z = b2[c+2] + b2[FOUT+c+2] + b2[2*FOUT+c+2] + b2[3*FOUT+c+2];
        v.w = b2[c+3] + b2[FOUT+c+3] + b2[2*FOUT+c+3] + b2[3*FOUT+c+3];
        out4[j] = v;
    }
}

// ---------------------------------------------------------------------------
// Degrees: int histogram on dst (drives dinv_in + CSR), float accum on src
// ---------------------------------------------------------------------------
__global__ void degree_kernel(const int* __restrict__ src, const int* __restrict__ dst) {
    int t = blockIdx.x * blockDim.x + threadIdx.x;
    if (t >= RR * EE) return;
    int r = t / EE;
    atomicAdd(&g_cnt[r * NN + dst[t]], 1);
    atomicAdd(&g_dinv_out[r * NN + src[t]], 1.0f);
}

// rsqrt of degrees + sb1 = sum_r b1[r]
__global__ void rsqrt_kernel(const float* __restrict__ b1) {
    int t = blockIdx.x * blockDim.x + threadIdx.x;
    if (t < FHID) {
        float s = 0.f;
        #pragma unroll
        for (int r = 0; r < RR; r++) s += b1[r * FHID + t];
        g_sb1[t] = s;
    }
    if (t >= NSC) return;
    g_dinv_out[t] = rsqrtf(fmaxf(g_dinv_out[t], 1.0f));
    g_dinv_in [t] = rsqrtf(fmaxf((float)g_cnt[t], 1.0f));
}

// ---------------------------------------------------------------------------
// Two-level exclusive scan of g_cnt -> g_rowptr (+ g_wptr copy)
// ---------------------------------------------------------------------------
__global__ void scan1() {           // per-block exclusive scan, 1024 elems/block
    __shared__ int sh[256];
    int tid = threadIdx.x;
    int i0 = blockIdx.x * 1024 + tid * 4;
    int a0 = (i0 + 0 < NSC) ? g_cnt[i0 + 0] : 0;
    int a1 = (i0 + 1 < NSC) ? g_cnt[i0 + 1] : 0;
    int a2 = (i0 + 2 < NSC) ? g_cnt[i0 + 2] : 0;
    int a3 = (i0 + 3 < NSC) ? g_cnt[i0 + 3] : 0;
    int s0 = a0, s1 = s0 + a1, s2 = s1 + a2, s3 = s2 + a3;  // local inclusive
    sh[tid] = s3;
    __syncthreads();
    for (int d = 1; d < 256; d <<= 1) {
        int v = (tid >= d) ? sh[tid - d] : 0;
        __syncthreads();
        sh[tid] += v;
        __syncthreads();
    }
    int ex = sh[tid] - s3;                                   // exclusive thread prefix
    if (i0 + 0 < NSC) g_rowptr[i0 + 0] = ex;
    if (i0 + 1 < NSC) g_rowptr[i0 + 1] = ex + s0;
    if (i0 + 2 < NSC) g_rowptr[i0 + 2] = ex + s1;
    if (i0 + 3 < NSC) g_rowptr[i0 + 3] = ex + s2;
    if (tid == 255) g_bsum[blockIdx.x] = sh[255];
}

__global__ void scan2() {           // single-block exclusive scan of block sums
    __shared__ int sh[512];
    int tid = threadIdx.x;
    int v = (tid < NB) ? g_bsum[tid] : 0;
    sh[tid] = v;
    __syncthreads();
    for (int d = 1; d < 512; d <<= 1) {
        int u = (tid >= d) ? sh[tid - d] : 0;
        __syncthreads();
        sh[tid] += u;
        __syncthreads();
    }
    if (tid < NB) g_bsum[tid] = sh[tid] - v;                 // exclusive
}

__global__ void scan3() {           // add block offsets; copy to write cursors
    int add = g_bsum[blockIdx.x];
    int i0 = blockIdx.x * 1024 + threadIdx.x * 4;
    #pragma unroll
    for (int j = 0; j < 4; j++) {
        int i = i0 + j;
        if (i < NSC) {
            int v = g_rowptr[i] + add;
            g_rowptr[i] = v;
            g_wptr[i] = v;
        }
    }
}

// Placement: dst-sorted src list per relation (ticket via atomic cursor)
__global__ void place_kernel(const int* __restrict__ src, const int* __restrict__ dst) {
    int t = blockIdx.x * blockDim.x + threadIdx.x;
    if (t >= RR * EE) return;
    int r = t / EE;
    int pos = atomicAdd(&g_wptr[r * NN + dst[t]], 1);
    g_srt[pos] = src[t];
}

// ---------------------------------------------------------------------------
// TF32 helpers
// ---------------------------------------------------------------------------
__device__ __forceinline__ uint32_t f2tf32(float x) {
    uint32_t u;
    asm("cvt.rna.tf32.f32 %0, %1;" : "=r"(u) : "f"(x));
    return u;
}

__device__ __forceinline__ void mma_tf32(float* c, const uint32_t* a,
                                         uint32_t b0, uint32_t b1) {
    asm volatile(
        "mma.sync.aligned.m16n8k8.row.col.f32.tf32.tf32.f32 "
        "{%0,%1,%2,%3}, {%4,%5,%6,%7}, {%8,%9}, {%0,%1,%2,%3};"
        : "+f"(c[0]), "+f"(c[1]), "+f"(c[2]), "+f"(c[3])
        : "r"(a[0]), "r"(a[1]), "r"(a[2]), "r"(a[3]), "r"(b0), "r"(b1));
}

// ---------------------------------------------------------------------------
// Tensor-core TF32 GEMM (one relation r per launch), writes g_h16 (fp16):
//   g_h16[m][n] = half( g_dinv_out[r][m] * sum_k f(A[m][k]) * W[r][k][n] )
// LAYER2: A = g_acc1, f(a) = relu(a + g_sb1[k]); else A = A_in.
// (unchanged from R11 — validated)
// ---------------------------------------------------------------------------
template <int BN, bool LAYER2>
__global__ void __launch_bounds__(256, 2)
gemm_tc(const float* __restrict__ A_in,
        const float* __restrict__ W,
        int M, int K, int r)
{
    constexpr int BM = 128, BK = 32;
    constexpr int APT  = BM * BK / 4 / 256;
    constexpr int BPT  = BK * BN / 4 / 256;
    constexpr int ASTR = BK + 4;
    constexpr int BSTR = BN + 8;
    constexpr int WN   = BN / 2;
    constexpr int NT   = WN / 8;

    __shared__ uint32_t As[BM * ASTR];
    __shared__ uint32_t Bs[BK * BSTR];

    const float* A = LAYER2 ? g_acc1 : A_in;
    const float* B = W + (size_t)r * K * BN;

    const int tid  = threadIdx.x;
    const int wid  = tid >> 5;
    const int lane = tid & 31;
    const int g    = lane >> 2;
    const int tig  = lane & 3;
    const int warp_m = wid & 3;
    const int warp_n = wid >> 2;
    const int rowBase = blockIdx.x * BM;

    float acc[2][NT][4];
    #pragma unroll
    for (int mt = 0; mt < 2; mt++)
        #pragma unroll
        for (int nt = 0; nt < NT; nt++)
            #pragma unroll
            for (int j = 0; j < 4; j++) acc[mt][nt][j] = 0.f;

    float4 aReg[APT], bReg[BPT];

    auto load_regs = [&](int k0) {
        #pragma unroll
        for (int i = 0; i < APT; i++) {
            int f = i * 256 + tid;
            int arow = f >> 3;
            int ac4  = f & 7;
            int grow = rowBase + arow;
            float4 v = make_float4(0.f, 0.f, 0.f, 0.f);
            if (grow < M)
                v = *(const float4*)(A + (size_t)grow * K + k0 + ac4 * 4);
            aReg[i] = v;
        }
        #pragma unroll
        for (int i = 0; i < BPT; i++) {
            int f = i * 256 + tid;
            int brow = f / (BN / 4);
            int bc4  = f % (BN / 4);
            bReg[i] = *(const float4*)(B + (size_t)(k0 + brow) * BN + bc4 * 4);
        }
    };

    auto store_smem = [&](int kload) {
        #pragma unroll
        for (int i = 0; i < APT; i++) {
            int f = i * 256 + tid;
            int arow = f >> 3;
            int ac4  = f & 7;
            float4 v = aReg[i];
            if (LAYER2) {
                const float* bb = g_sb1 + kload + ac4 * 4;
                v.x = fmaxf(v.x + bb[0], 0.f);
                v.y = fmaxf(v.y + bb[1], 0.f);
                v.z = fmaxf(v.z + bb[2], 0.f);
                v.w = fmaxf(v.w + bb[3], 0.f);
            }
            uint4 u = make_uint4(f2tf32(v.x), f2tf32(v.y), f2tf32(v.z), f2tf32(v.w));
            *(uint4*)&As[arow * ASTR + ac4 * 4] = u;
        }
        #pragma unroll
        for (int i = 0; i < BPT; i++) {
            int f = i * 256 + tid;
            int brow = f / (BN / 4);
            int bc4  = f % (BN / 4);
            float4 v = bReg[i];
            uint4 u = make_uint4(f2tf32(v.x), f2tf32(v.y), f2tf32(v.z), f2tf32(v.w));
            *(uint4*)&Bs[brow * BSTR + bc4 * 4] = u;
        }
    };

    auto compute = [&]() {
        #pragma unroll
        for (int ks = 0; ks < 4; ks++) {
            int k8 = ks * 8;
            uint32_t a[2][4];
            #pragma unroll
            for (int mt = 0; mt < 2; mt++) {
                int rb = warp_m * 32 + mt * 16;
                a[mt][0] = As[(rb + g)     * ASTR + k8 + tig];
                a[mt][1] = As[(rb + g + 8) * ASTR + k8 + tig];
                a[mt][2] = As[(rb + g)     * ASTR + k8 + tig + 4];
                a[mt][3] = As[(rb + g + 8) * ASTR + k8 + tig + 4];
            }
            #pragma unroll
            for (int nt = 0; nt < NT; nt++) {
                int cb = warp_n * WN + nt * 8;
                uint32_t b0 = Bs[(k8 + tig)     * BSTR + cb + g];
                uint32_t b1 = Bs[(k8 + tig + 4) * BSTR + cb + g];
                #pragma unroll
                for (int mt = 0; mt < 2; mt++)
                    mma_tf32(acc[mt][nt], a[mt], b0, b1);
            }
        }
    };

    load_regs(0);
    store_smem(0);
    __syncthreads();
    for (int k0 = BK; k0 < K; k0 += BK) {
        load_regs(k0);
        compute();
        __syncthreads();
        store_smem(k0);
        __syncthreads();
    }
    compute();

    #pragma unroll
    for (int mt = 0; mt < 2; mt++) {
        int row0 = rowBase + warp_m * 32 + mt * 16 + g;
        int row1 = row0 + 8;
        float s0 = (row0 < M) ? g_dinv_out[(size_t)r * NN + row0] : 0.f;
        float s1 = (row1 < M) ? g_dinv_out[(size_t)r * NN + row1] : 0.f;
        #pragma unroll
        for (int nt = 0; nt < NT; nt++) {
            int col = warp_n * WN + nt * 8 + 2 * tig;
            if (row0 < M)
                *(__half2*)&g_h16[(size_t)row0 * BN + col] =
                    __floats2half2_rn(acc[mt][nt][0] * s0, acc[mt][nt][1] * s0);
            if (row1 < M)
                *(__half2*)&g_h16[(size_t)row1 * BN + col] =
                    __floats2half2_rn(acc[mt][nt][2] * s1, acc[mt][nt][3] * s1);
        }
    }
}

// ---------------------------------------------------------------------------
// CSR gather-aggregation: one warp per dst node, NO atomics.
// Relations run sequentially, each dst owned by exactly one warp -> plain RMW.
// Dual accumulator breaks the L2-latency dependence chain (avg 5 edges/dst).
// ---------------------------------------------------------------------------
__device__ __forceinline__ void h4_acc(float4& a, uint2 raw) {
    float2 f01 = __half22float2(*(__half2*)&raw.x);
    float2 f23 = __half22float2(*(__half2*)&raw.y);
    a.x += f01.x; a.y += f01.y; a.z += f23.x; a.w += f23.y;
}

// Layer 1: g_acc1[d] += dinv_in[r][d] * sum_{e in CSR_r[d]} h16[src_e]  (128 feats)
__global__ void __launch_bounds__(256)
gather128(int r) {
    int w = (blockIdx.x * blockDim.x + threadIdx.x) >> 5;
    if (w >= NN) return;
    int lane = threadIdx.x & 31;
    int idx = r * NN + w;
    int beg = g_rowptr[idx];
    int end = (idx == NSC - 1) ? RR * EE : g_rowptr[idx + 1];
    if (beg == end) return;
    const uint2* h = (const uint2*)g_h16;
    float4 a0 = make_float4(0.f, 0.f, 0.f, 0.f);
    float4 a1 = make_float4(0.f, 0.f, 0.f, 0.f);
    int e = beg;
    for (; e + 2 <= end; e += 2) {
        int s0 = g_srt[e], s1 = g_srt[e + 1];
        uint2 r0 = h[(size_t)s0 * (FHID / 4) + lane];
        uint2 r1 = h[(size_t)s1 * (FHID / 4) + lane];
        h4_acc(a0, r0);
        h4_acc(a1, r1);
    }
    if (e < end) {
        uint2 r0 = h[(size_t)g_srt[e] * (FHID / 4) + lane];
        h4_acc(a0, r0);
    }
    float sc = g_dinv_in[idx];
    float4* acc4 = (float4*)g_acc1;
    size_t o = (size_t)w * (FHID / 4) + lane;
    float4 cur = acc4[o];
    cur.x += sc * (a0.x + a1.x);
    cur.y += sc * (a0.y + a1.y);
    cur.z += sc * (a0.z + a1.z);
    cur.w += sc * (a0.w + a1.w);
    acc4[o] = cur;
}

// Layer 2: out[d] += dinv_in[r][d] * sum h16[src]  (64 feats; lane = half2)
__global__ void __launch_bounds__(256)
gather64(float* __restrict__ out, int r) {
    int w = (blockIdx.x * blockDim.x + threadIdx.x) >> 5;
    if (w >= NN) return;
    int lane = threadIdx.x & 31;
    int idx = r * NN + w;
    int beg = g_rowptr[idx];
    int end = (idx == NSC - 1) ? RR * EE : g_rowptr[idx + 1];
    if (beg == end) return;
    const uint32_t* h = (const uint32_t*)g_h16;
    float2 a0 = make_float2(0.f, 0.f);
    float2 a1 = make_float2(0.f, 0.f);
    int e = beg;
    for (; e + 2 <= end; e += 2) {
        uint32_t r0 = h[(size_t)g_srt[e]     * (FOUT / 2) + lane];
        uint32_t r1 = h[(size_t)g_srt[e + 1] * (FOUT / 2) + lane];
        float2 f0 = __half22float2(*(__half2*)&r0);
        float2 f1 = __half22float2(*(__half2*)&r1);
        a0.x += f0.x; a0.y += f0.y;
        a1.x += f1.x; a1.y += f1.y;
    }
    if (e < end) {
        uint32_t r0 = h[(size_t)g_srt[e] * (FOUT / 2) + lane];
        float2 f0 = __half22float2(*(__half2*)&r0);
        a0.x += f0.x; a0.y += f0.y;
    }
    float sc = g_dinv_in[idx];
    float2* o2 = (float2*)out;
    size_t o = (size_t)w * (FOUT / 2) + lane;
    float2 cur = o2[o];
    cur.x += sc * (a0.x + a1.x);
    cur.y += sc * (a0.y + a1.y);
    o2[o] = cur;
}

// ---------------------------------------------------------------------------
// Launch — only genuine harness pointers cross host/device.
// ---------------------------------------------------------------------------
extern "C" void kernel_launch(void* const* d_in, const int* in_sizes, int n_in,
                              void* d_out, int out_size) {
    const float* x = nullptr; const int* esrc = nullptr; const int* edst = nullptr;
    const float* W1 = nullptr; const float* b1 = nullptr;
    const float* W2 = nullptr; const float* b2 = nullptr;
    for (int i = 0; i < n_in; i++) {
        switch (in_sizes[i]) {
            case NN * FIN:       x  = (const float*)d_in[i]; break;
            case RR * EE:        if (!esrc) esrc = (const int*)d_in[i];
                                 else       edst = (const int*)d_in[i]; break;
            case RR * FIN * FHID:  W1 = (const float*)d_in[i]; break;
            case RR * FHID:        b1 = (const float*)d_in[i]; break;
            case RR * FHID * FOUT: W2 = (const float*)d_in[i]; break;
            case RR * FOUT:        b2 = (const float*)d_in[i]; break;
            default: break;
        }
    }
    if (!x || !esrc || !edst || !W1 || !b1 || !W2 || !b2) {
        x    = (const float*)d_in[0];
        esrc = (const int*)  d_in[1];
        edst = (const int*)  d_in[2];
        W1   = (const float*)d_in[3];
        b1   = (const float*)d_in[4];
        W2   = (const float*)d_in[5];
        b2   = (const float*)d_in[6];
    }
    float* out = (float*)d_out;

    // 1) zero scratch; out <- broadcast sum_r b2[r]
    zero_all<<<2048, 256>>>((float4*)out, b2);

    // 2) degrees (int dst-histogram + float src accum) -> rsqrt; sb1
    degree_kernel<<<(RR * EE + 255) / 256, 256>>>(esrc, edst);
    rsqrt_kernel<<<(NSC + 255) / 256, 256>>>(b1);

    // 3) CSR build: exclusive scan of histogram, then dst-sorted placement
    scan1<<<NB, 256>>>();
    scan2<<<1, 512>>>();
    scan3<<<NB, 256>>>();
    place_kernel<<<(RR * EE + 255) / 256, 256>>>(esrc, edst);

    dim3 ggrid((NN + 127) / 128, 1, 1);
    int gather_grid = (NN * 32 + 255) / 256;

    // 4) layer 1, per relation (h16 + acc1 L2-resident, no atomics):
    for (int r = 0; r < RR; r++) {
        gemm_tc<FHID, false><<<ggrid, 256>>>(x, W1, NN, FIN, r);
        gather128<<<gather_grid, 256>>>(r);
    }

    // 5) layer 2, per relation, fused relu(acc1 + sb1) at the A-stage:
    for (int r = 0; r < RR; r++) {
        gemm_tc<FOUT, true><<<ggrid, 256>>>(nullptr, W2, NN, FHID, r);
        gather64<<<gather_grid, 256>>>(out, r);
    }
}